// round 7
// baseline (speedup 1.0000x reference)
#include <cuda_runtime.h>
#include <cuda_fp16.h>
#include <cstdint>

#define N_NODES 16384
#define D_IN 128
#define SEQL 128
#define HEADS 4
#define CH 64
#define F1 256
#define E_EDGES 262144
#define CAP 64           // slots per destination (P(deg>64) ~ 1e-19)

// ---------------- scratch (static device globals; no allocation) -------------
__device__ __half g_h1h[N_NODES * F1];    // layer-1 features (fp16, gather-only)
__device__ float g_out1[N_NODES * F1];    // layer-1 aggregation result
__device__ float g_asrc1[N_NODES * HEADS];
__device__ float g_adst1[N_NODES * HEADS];
__device__ float g_h2[N_NODES * CH];      // layer-2 features
__device__ float g_asrc2[N_NODES];
__device__ float g_adst2[N_NODES];
// slotted adjacency (dst-binned; self-loops handled implicitly)
__device__ int g_cur[N_NODES];
__device__ int g_slot[N_NODES * CAP];

__device__ __forceinline__ float lrelu(float v) { return v > 0.f ? v : 0.2f * v; }
__device__ __forceinline__ float elu1(float v) { return v > 0.f ? v : expm1f(v); }
__device__ __forceinline__ uint32_t h2u(__half2 h) { return *reinterpret_cast<uint32_t*>(&h); }

// ---- packed f32x2 helpers (sm_100+) ----
typedef unsigned long long ull;
__device__ __forceinline__ void ffma2(ull& acc, ull a, ull b) {
    asm("fma.rn.f32x2 %0, %1, %2, %0;" : "+l"(acc) : "l"(a), "l"(b));
}
__device__ __forceinline__ void fmul2(ull& a, ull b) {
    asm("mul.rn.f32x2 %0, %0, %1;" : "+l"(a) : "l"(b));
}
__device__ __forceinline__ ull bc2(float x) {
    ull r;
    unsigned u = __float_as_uint(x);
    asm("mov.b64 %0, {%1, %1};" : "=l"(r) : "r"(u));
    return r;
}
__device__ __forceinline__ void unpk2(ull v, float& lo, float& hi) {
    asm("mov.b64 {%0, %1}, %2;" : "=f"(lo), "=f"(hi) : "l"(v));
}
union F2U { float2 f; ull u; };

// fp16 uint4 (8 values) * scalar -> 4 packed f32x2 accumulators
__device__ __forceinline__ void hacc(ull* acc2, uint4 v, float af) {
    ull a = bc2(af);
    F2U c0, c1, c2, c3;
    c0.f = __half22float2(*(__half2*)&v.x);
    c1.f = __half22float2(*(__half2*)&v.y);
    c2.f = __half22float2(*(__half2*)&v.z);
    c3.f = __half22float2(*(__half2*)&v.w);
    ffma2(acc2[0], a, c0.u);
    ffma2(acc2[1], a, c1.u);
    ffma2(acc2[2], a, c2.u);
    ffma2(acc2[3], a, c3.u);
}

// ---------------- adjacency build --------------------------------------------
__global__ void k_zero() {
    int i = blockIdx.x * blockDim.x + threadIdx.x;     // 4096 threads
    *(int4*)&g_cur[i * 4] = make_int4(0, 0, 0, 0);
}
__global__ void k_fill(const int* __restrict__ ei) {
    int e = blockIdx.x * blockDim.x + threadIdx.x;     // 262144 threads
    int ss = ei[e];
    int dd = ei[E_EDGES + e];
    int pos = atomicAdd(&g_cur[dd], 1);
    if (pos < CAP) g_slot[(dd << 6) + pos] = ss;
}

// ---------------- GEMM1: h1 = (x*sqrt(D) + pe) @ W1, fused alpha dots --------
// BM=64, BN=64(head), BK=32, 128 threads, microtile 8 rows x 4 cols, FFMA2.
// B stored duplicated ({b,b} pairs) so broadcast pairs come straight from LDS.128.
__global__ void __launch_bounds__(128) k_gemm1(
        const float* __restrict__ x, const float* __restrict__ pe,
        const float* __restrict__ W1,
        const float* __restrict__ a_src1, const float* __restrict__ a_dst1) {
    const int head = blockIdx.y;
    const int rowBase = blockIdx.x * 64;
    __shared__ float Ak[32][64];       // K-major
    __shared__ float Bs2[32][128];     // duplicated B
    __shared__ float sa[64], sd[64];

    const int tid = threadIdx.x;
    const int tx = tid & 15;          // col quad: cols tx*4..+3
    const int ty = tid >> 4;          // row octet: rows ty*8..+7
    if (tid < 64) { sa[tid] = a_src1[head * 64 + tid]; sd[tid] = a_dst1[head * 64 + tid]; }

    ull acc2[4][4];
#pragma unroll
    for (int i = 0; i < 4; i++)
#pragma unroll
        for (int j = 0; j < 4; j++) acc2[i][j] = 0ull;

    const float SC = 11.313708498984760f; // sqrt(128)
    const int ar = tid & 63;              // A fill: row
    const int kb = (tid >> 6) * 16;       // A fill: k half (16 floats)
    const float* xr = x + (rowBase + ar) * D_IN;
    const float* pr = pe + ((rowBase + ar) & (SEQL - 1)) * D_IN;

    for (int k0 = 0; k0 < D_IN; k0 += 32) {
#pragma unroll
        for (int q = 0; q < 4; q++) {
            float4 xv = *(const float4*)&xr[k0 + kb + q * 4];
            float4 pv = *(const float4*)&pr[k0 + kb + q * 4];
            Ak[kb + q * 4 + 0][ar] = xv.x * SC + pv.x;
            Ak[kb + q * 4 + 1][ar] = xv.y * SC + pv.y;
            Ak[kb + q * 4 + 2][ar] = xv.z * SC + pv.z;
            Ak[kb + q * 4 + 3][ar] = xv.w * SC + pv.w;
        }
#pragma unroll
        for (int q = 0; q < 4; q++) {
            int v = tid * 4 + q;      // 0..511
            int r = v >> 4, c = v & 15;
            float4 wv = *(const float4*)&W1[(k0 + r) * F1 + head * 64 + c * 4];
            float2* bp = (float2*)&Bs2[r][c * 8];
            bp[0] = make_float2(wv.x, wv.x);
            bp[1] = make_float2(wv.y, wv.y);
            bp[2] = make_float2(wv.z, wv.z);
            bp[3] = make_float2(wv.w, wv.w);
        }
        __syncthreads();
#pragma unroll
        for (int kk = 0; kk < 32; kk++) {
            ulonglong2 ap01 = *(ulonglong2*)&Ak[kk][ty * 8];      // row pairs 0,1
            ulonglong2 ap23 = *(ulonglong2*)&Ak[kk][ty * 8 + 4];  // row pairs 2,3
            ulonglong2 bp01 = *(ulonglong2*)&Bs2[kk][tx * 8];
            ulonglong2 bp23 = *(ulonglong2*)&Bs2[kk][tx * 8 + 4];
            ull b0 = bp01.x, b1 = bp01.y, b2 = bp23.x, b3 = bp23.y;
            ffma2(acc2[0][0], ap01.x, b0); ffma2(acc2[0][1], ap01.x, b1);
            ffma2(acc2[0][2], ap01.x, b2); ffma2(acc2[0][3], ap01.x, b3);
            ffma2(acc2[1][0], ap01.y, b0); ffma2(acc2[1][1], ap01.y, b1);
            ffma2(acc2[1][2], ap01.y, b2); ffma2(acc2[1][3], ap01.y, b3);
            ffma2(acc2[2][0], ap23.x, b0); ffma2(acc2[2][1], ap23.x, b1);
            ffma2(acc2[2][2], ap23.x, b2); ffma2(acc2[2][3], ap23.x, b3);
            ffma2(acc2[3][0], ap23.y, b0); ffma2(acc2[3][1], ap23.y, b1);
            ffma2(acc2[3][2], ap23.y, b2); ffma2(acc2[3][3], ap23.y, b3);
        }
        __syncthreads();
    }

    // epilogue: per row-pair, fp16 store + alpha dots (reduce over 16 tx lanes)
#pragma unroll
    for (int rp = 0; rp < 4; rp++) {
        float alo[4], ahi[4];
#pragma unroll
        for (int c = 0; c < 4; c++) unpk2(acc2[rp][c], alo[c], ahi[c]);
        int rlo = rowBase + ty * 8 + rp * 2;
        int rhi = rlo + 1;
        __half2 l0 = __floats2half2_rn(alo[0], alo[1]);
        __half2 l1 = __floats2half2_rn(alo[2], alo[3]);
        __half2 h0 = __floats2half2_rn(ahi[0], ahi[1]);
        __half2 h1 = __floats2half2_rn(ahi[2], ahi[3]);
        *(uint2*)&g_h1h[rlo * F1 + head * 64 + tx * 4] = make_uint2(h2u(l0), h2u(l1));
        *(uint2*)&g_h1h[rhi * F1 + head * 64 + tx * 4] = make_uint2(h2u(h0), h2u(h1));
        float pslo = 0.f, pdlo = 0.f, pshi = 0.f, pdhi = 0.f;
#pragma unroll
        for (int c = 0; c < 4; c++) {
            float wa = sa[tx * 4 + c], wd = sd[tx * 4 + c];
            pslo += alo[c] * wa; pdlo += alo[c] * wd;
            pshi += ahi[c] * wa; pdhi += ahi[c] * wd;
        }
#pragma unroll
        for (int o = 1; o < 16; o <<= 1) {
            pslo += __shfl_xor_sync(0xffffffffu, pslo, o);
            pdlo += __shfl_xor_sync(0xffffffffu, pdlo, o);
            pshi += __shfl_xor_sync(0xffffffffu, pshi, o);
            pdhi += __shfl_xor_sync(0xffffffffu, pdhi, o);
        }
        if (tx == 0) {
            g_asrc1[rlo * HEADS + head] = pslo;
            g_adst1[rlo * HEADS + head] = pdlo;
            g_asrc1[rhi * HEADS + head] = pshi;
            g_adst1[rhi * HEADS + head] = pdhi;
        }
    }
}

// ---------------- layer-1 fused softmax + aggregate (warp per dst) -----------
// Deferred-rden: accumulate with raw exp weights, scale once at the end.
__global__ void __launch_bounds__(256, 4) k_agg1() {
    __shared__ __align__(16) float s_al[8][4][40];   // [warp][head][entry] raw exp
    __shared__ __align__(16) int s_src[8][40];
    const int wip = threadIdx.x >> 5;
    const int w = (blockIdx.x * blockDim.x + threadIdx.x) >> 5;
    const int lane = threadIdx.x & 31;
    if (w >= N_NODES) return;
    const int start = w << 6;
    const int cnt = min(g_cur[w], CAP);
    const float4 ad = *(const float4*)&g_adst1[w * 4];
    const float4 asw = *(const float4*)&g_asrc1[w * 4];
    const float4 exself = make_float4(__expf(lrelu(asw.x + ad.x)), __expf(lrelu(asw.y + ad.y)),
                                      __expf(lrelu(asw.z + ad.z)), __expf(lrelu(asw.w + ad.w)));
    const int h = lane >> 3;
    ull acc2[4] = {0ull, 0ull, 0ull, 0ull};
    float4 rden;

    if (cnt <= 32) {
        // ---- fast path: self folded in as entry 0, edges at 1..cnt, zero pads ----
        int s = w;
        float4 ex = make_float4(0.f, 0.f, 0.f, 0.f);
        if (lane < cnt) {
            s = g_slot[start + lane];
            float4 as = *(const float4*)&g_asrc1[s * 4];
            ex = make_float4(__expf(lrelu(as.x + ad.x)), __expf(lrelu(as.y + ad.y)),
                             __expf(lrelu(as.z + ad.z)), __expf(lrelu(as.w + ad.w)));
        }
        float4 den = ex;
#pragma unroll
        for (int o = 16; o > 0; o >>= 1) {
            den.x += __shfl_xor_sync(0xffffffffu, den.x, o);
            den.y += __shfl_xor_sync(0xffffffffu, den.y, o);
            den.z += __shfl_xor_sync(0xffffffffu, den.z, o);
            den.w += __shfl_xor_sync(0xffffffffu, den.w, o);
        }
        rden = make_float4(1.f / (den.x + exself.x + 1e-16f), 1.f / (den.y + exself.y + 1e-16f),
                           1.f / (den.z + exself.z + 1e-16f), 1.f / (den.w + exself.w + 1e-16f));
        // raw weights into smem
        s_al[wip][0][lane + 1] = ex.x;
        s_al[wip][1][lane + 1] = ex.y;
        s_al[wip][2][lane + 1] = ex.z;
        s_al[wip][3][lane + 1] = ex.w;
        s_src[wip][lane + 1] = s;
        if (lane == 0) {
            s_src[wip][0] = w;
            s_al[wip][0][0] = exself.x;
            s_al[wip][1][0] = exself.y;
            s_al[wip][2][0] = exself.z;
            s_al[wip][3][0] = exself.w;
        }
        if (lane >= 1 && lane < 8) {           // pads 33..39
            int e = 32 + lane;
            s_al[wip][0][e] = 0.f; s_al[wip][1][e] = 0.f;
            s_al[wip][2][e] = 0.f; s_al[wip][3][e] = 0.f;
            s_src[wip][e] = w;
        }
        __syncwarp();

        const int tp8 = (cnt + 8) & ~7;        // (cnt+1) padded to mult of 8
        const float* alrow = &s_al[wip][h][0];
        const int* srow = &s_src[wip][0];
        for (int j = 0; j < tp8; j += 8) {
            int4 sA = *(const int4*)&srow[j];
            int4 sB = *(const int4*)&srow[j + 4];
            uint4 v0 = *(const uint4*)&g_h1h[sA.x * F1 + lane * 8];
            uint4 v1 = *(const uint4*)&g_h1h[sA.y * F1 + lane * 8];
            uint4 v2 = *(const uint4*)&g_h1h[sA.z * F1 + lane * 8];
            uint4 v3 = *(const uint4*)&g_h1h[sA.w * F1 + lane * 8];
            uint4 v4 = *(const uint4*)&g_h1h[sB.x * F1 + lane * 8];
            uint4 v5 = *(const uint4*)&g_h1h[sB.y * F1 + lane * 8];
            uint4 v6 = *(const uint4*)&g_h1h[sB.z * F1 + lane * 8];
            uint4 v7 = *(const uint4*)&g_h1h[sB.w * F1 + lane * 8];
            float4 afA = *(const float4*)&alrow[j];
            float4 afB = *(const float4*)&alrow[j + 4];
            hacc(acc2, v0, afA.x); hacc(acc2, v1, afA.y);
            hacc(acc2, v2, afA.z); hacc(acc2, v3, afA.w);
            hacc(acc2, v4, afB.x); hacc(acc2, v5, afB.y);
            hacc(acc2, v6, afB.z); hacc(acc2, v7, afB.w);
        }
    } else {
        // ---- general path (rare: 32 < deg <= 64) ----
        float4 den = exself;
        for (int base = 0; base < cnt; base += 32) {
            int idx = base + lane;
            float4 ex = make_float4(0.f, 0.f, 0.f, 0.f);
            if (idx < cnt) {
                int s = g_slot[start + idx];
                float4 as = *(const float4*)&g_asrc1[s * 4];
                ex = make_float4(__expf(lrelu(as.x + ad.x)), __expf(lrelu(as.y + ad.y)),
                                 __expf(lrelu(as.z + ad.z)), __expf(lrelu(as.w + ad.w)));
            }
#pragma unroll
            for (int o = 16; o > 0; o >>= 1) {
                ex.x += __shfl_xor_sync(0xffffffffu, ex.x, o);
                ex.y += __shfl_xor_sync(0xffffffffu, ex.y, o);
                ex.z += __shfl_xor_sync(0xffffffffu, ex.z, o);
                ex.w += __shfl_xor_sync(0xffffffffu, ex.w, o);
            }
            den.x += ex.x; den.y += ex.y; den.z += ex.z; den.w += ex.w;
        }
        rden = make_float4(1.f / (den.x + 1e-16f), 1.f / (den.y + 1e-16f),
                           1.f / (den.z + 1e-16f), 1.f / (den.w + 1e-16f));
        float exh = (h & 2) ? ((h & 1) ? exself.w : exself.z) : ((h & 1) ? exself.y : exself.x);
        {   // self (raw weight)
            uint4 v = *(const uint4*)&g_h1h[w * F1 + lane * 8];
            hacc(acc2, v, exh);
        }
        for (int base = 0; base < cnt; base += 32) {
            int idx = base + lane;
            int s = w;
            float4 al = make_float4(0.f, 0.f, 0.f, 0.f);
            if (idx < cnt) {
                s = g_slot[start + idx];
                float4 as = *(const float4*)&g_asrc1[s * 4];
                al = make_float4(__expf(lrelu(as.x + ad.x)), __expf(lrelu(as.y + ad.y)),
                                 __expf(lrelu(as.z + ad.z)), __expf(lrelu(as.w + ad.w)));
            }
            __syncwarp();
            s_al[wip][0][lane] = al.x; s_al[wip][1][lane] = al.y;
            s_al[wip][2][lane] = al.z; s_al[wip][3][lane] = al.w;
            s_src[wip][lane] = s;
            if (lane < 8) {   // pads 32..39 zeroed
                s_al[wip][0][32 + lane] = 0.f; s_al[wip][1][32 + lane] = 0.f;
                s_al[wip][2][32 + lane] = 0.f; s_al[wip][3][32 + lane] = 0.f;
                s_src[wip][32 + lane] = w;
            }
            __syncwarp();
            int c = min(32, cnt - base);
            int cp = (c + 7) & ~7;
            const float* alrow = &s_al[wip][h][0];
            const int* srow = &s_src[wip][0];
            for (int j = 0; j < cp; j += 8) {
                int4 sA = *(const int4*)&srow[j];
                int4 sB = *(const int4*)&srow[j + 4];
                uint4 v0 = *(const uint4*)&g_h1h[sA.x * F1 + lane * 8];
                uint4 v1 = *(const uint4*)&g_h1h[sA.y * F1 + lane * 8];
                uint4 v2 = *(const uint4*)&g_h1h[sA.z * F1 + lane * 8];
                uint4 v3 = *(const uint4*)&g_h1h[sA.w * F1 + lane * 8];
                uint4 v4 = *(const uint4*)&g_h1h[sB.x * F1 + lane * 8];
                uint4 v5 = *(const uint4*)&g_h1h[sB.y * F1 + lane * 8];
                uint4 v6 = *(const uint4*)&g_h1h[sB.z * F1 + lane * 8];
                uint4 v7 = *(const uint4*)&g_h1h[sB.w * F1 + lane * 8];
                float4 afA = *(const float4*)&alrow[j];
                float4 afB = *(const float4*)&alrow[j + 4];
                hacc(acc2, v0, afA.x); hacc(acc2, v1, afA.y);
                hacc(acc2, v2, afA.z); hacc(acc2, v3, afA.w);
                hacc(acc2, v4, afB.x); hacc(acc2, v5, afB.y);
                hacc(acc2, v6, afB.z); hacc(acc2, v7, afB.w);
            }
            __syncwarp();
        }
    }
    float rdh = (h & 2) ? ((h & 1) ? rden.w : rden.z) : ((h & 1) ? rden.y : rden.x);
    ull r2 = bc2(rdh);
    fmul2(acc2[0], r2); fmul2(acc2[1], r2); fmul2(acc2[2], r2); fmul2(acc2[3], r2);
    float o0, o1, o2, o3, o4, o5, o6, o7;
    unpk2(acc2[0], o0, o1); unpk2(acc2[1], o2, o3);
    unpk2(acc2[2], o4, o5); unpk2(acc2[3], o6, o7);
    *(float4*)&g_out1[w * F1 + lane * 8] = make_float4(o0, o1, o2, o3);
    *(float4*)&g_out1[w * F1 + lane * 8 + 4] = make_float4(o4, o5, o6, o7);
}

// ---------------- GEMM2: h2 = elu(out1 + b1) @ W2, fused alpha dots ----------
__global__ void __launch_bounds__(128) k_gemm2(
        const float* __restrict__ b1, const float* __restrict__ W2,
        const float* __restrict__ a_src2, const float* __restrict__ a_dst2) {
    const int rowBase = blockIdx.x * 64;
    __shared__ float Ak[32][64];       // K-major
    __shared__ float Bs2[32][128];     // duplicated B
    __shared__ float sa[64], sd[64];
    __shared__ float sb1[F1];

    const int tid = threadIdx.x;
    const int tx = tid & 15;
    const int ty = tid >> 4;
    if (tid < 64) { sa[tid] = a_src2[tid]; sd[tid] = a_dst2[tid]; }
    sb1[tid] = b1[tid];
    sb1[tid + 128] = b1[tid + 128];
    __syncthreads();

    ull acc2[4][4];
#pragma unroll
    for (int i = 0; i < 4; i++)
#pragma unroll
        for (int j = 0; j < 4; j++) acc2[i][j] = 0ull;

    const int ar = tid & 63;
    const int kb = (tid >> 6) * 16;
    const float* orow = g_out1 + (rowBase + ar) * F1;

    for (int k0 = 0; k0 < F1; k0 += 32) {
#pragma unroll
        for (int q = 0; q < 4; q++) {
            float4 ov = *(const float4*)&orow[k0 + kb + q * 4];
            Ak[kb + q * 4 + 0][ar] = elu1(ov.x + sb1[k0 + kb + q * 4 + 0]);
            Ak[kb + q * 4 + 1][ar] = elu1(ov.y + sb1[k0 + kb + q * 4 + 1]);
            Ak[kb + q * 4 + 2][ar] = elu1(ov.z + sb1[k0 + kb + q * 4 + 2]);
            Ak[kb + q * 4 + 3][ar] = elu1(ov.w + sb1[k0 + kb + q * 4 + 3]);
        }
#pragma unroll
        for (int q = 0; q < 4; q++) {
            int v = tid * 4 + q;
            int r = v >> 4, c = v & 15;
            float4 wv = *(const float4*)&W2[(k0 + r) * CH + c * 4];
            float2* bp = (float2*)&Bs2[r][c * 8];
            bp[0] = make_float2(wv.x, wv.x);
            bp[1] = make_float2(wv.y, wv.y);
            bp[2] = make_float2(wv.z, wv.z);
            bp[3] = make_float2(wv.w, wv.w);
        }
        __syncthreads();
#pragma unroll
        for (int kk = 0; kk < 32; kk++) {
            ulonglong2 ap01 = *(ulonglong2*)&Ak[kk][ty * 8];
            ulonglong2 ap23 = *(ulonglong2*)&Ak[kk][ty * 8 + 4];
            ulonglong2 bp01 = *(ulonglong2*)&Bs2[kk][tx * 8];
            ulonglong2 bp23 = *(ulonglong2*)&Bs2[kk][tx * 8 + 4];
            ull b0 = bp01.x, b1v = bp01.y, b2 = bp23.x, b3 = bp23.y;
            ffma2(acc2[0][0], ap01.x, b0); ffma2(acc2[0][1], ap01.x, b1v);
            ffma2(acc2[0][2], ap01.x, b2); ffma2(acc2[0][3], ap01.x, b3);
            ffma2(acc2[1][0], ap01.y, b0); ffma2(acc2[1][1], ap01.y, b1v);
            ffma2(acc2[1][2], ap01.y, b2); ffma2(acc2[1][3], ap01.y, b3);
            ffma2(acc2[2][0], ap23.x, b0); ffma2(acc2[2][1], ap23.x, b1v);
            ffma2(acc2[2][2], ap23.x, b2); ffma2(acc2[2][3], ap23.x, b3);
            ffma2(acc2[3][0], ap23.y, b0); ffma2(acc2[3][1], ap23.y, b1v);
            ffma2(acc2[3][2], ap23.y, b2); ffma2(acc2[3][3], ap23.y, b3);
        }
        __syncthreads();
    }

#pragma unroll
    for (int rp = 0; rp < 4; rp++) {
        float alo[4], ahi[4];
#pragma unroll
        for (int c = 0; c < 4; c++) unpk2(acc2[rp][c], alo[c], ahi[c]);
        int rlo = rowBase + ty * 8 + rp * 2;
        int rhi = rlo + 1;
        *(float4*)&g_h2[rlo * CH + tx * 4] = make_float4(alo[0], alo[1], alo[2], alo[3]);
        *(float4*)&g_h2[rhi * CH + tx * 4] = make_float4(ahi[0], ahi[1], ahi[2], ahi[3]);
        float pslo = 0.f, pdlo = 0.f, pshi = 0.f, pdhi = 0.f;
#pragma unroll
        for (int c = 0; c < 4; c++) {
            float wa = sa[tx * 4 + c], wd = sd[tx * 4 + c];
            pslo += alo[c] * wa; pdlo += alo[c] * wd;
            pshi += ahi[c] * wa; pdhi += ahi[c] * wd;
        }
#pragma unroll
        for (int o = 1; o < 16; o <<= 1) {
            pslo += __shfl_xor_sync(0xffffffffu, pslo, o);
            pdlo += __shfl_xor_sync(0xffffffffu, pdlo, o);
            pshi += __shfl_xor_sync(0xffffffffu, pshi, o);
            pdhi += __shfl_xor_sync(0xffffffffu, pdhi, o);
        }
        if (tx == 0) {
            g_asrc2[rlo] = pslo; g_adst2[rlo] = pdlo;
            g_asrc2[rhi] = pshi; g_adst2[rhi] = pdhi;
        }
    }
}

// ---------------- layer-2 fused softmax + aggregate (warp per dst) -----------
__global__ void __launch_bounds__(256, 4) k_agg2(float* __restrict__ dout,
                                                 const float* __restrict__ b2) {
    __shared__ __align__(16) float s_ex[8][40];
    __shared__ __align__(16) int s_sr[8][40];
    const int wip = threadIdx.x >> 5;
    const int w = (blockIdx.x * blockDim.x + threadIdx.x) >> 5;
    const int lane = threadIdx.x & 31;
    if (w >= N_NODES) return;
    const int start = w << 6;
    const int cnt = min(g_cur[w], CAP);
    const float ad = g_adst2[w];
    const float exself = __expf(lrelu(g_asrc2[w] + ad));
    ull acc = 0ull;
    float rden;

    if (cnt <= 32) {
        int s = w;
        float ex = 0.f;
        if (lane < cnt) {
            s = g_slot[start + lane];
            ex = __expf(lrelu(g_asrc2[s] + ad));
        }
        float den = ex;
#pragma unroll
        for (int o = 16; o > 0; o >>= 1)
            den += __shfl_xor_sync(0xffffffffu, den, o);
        rden = 1.f / (den + exself + 1e-16f);
        s_ex[wip][lane + 1] = ex;
        s_sr[wip][lane + 1] = s;
        if (lane == 0) { s_ex[wip][0] = exself; s_sr[wip][0] = w; }
        if (lane >= 1 && lane < 8) { s_ex[wip][32 + lane] = 0.f; s_sr[wip][32 + lane] = w; }
        __syncwarp();

        const int tp8 = (cnt + 8) & ~7;
        const float* exrow = &s_ex[wip][0];
        const int* srow = &s_sr[wip][0];
        for (int j = 0; j < tp8; j += 8) {
            int4 sA = *(const int4*)&srow[j];
            int4 sB = *(const int4*)&srow[j + 4];
            F2U u0, u1, u2, u3, u4, u5, u6, u7;
            u0.f = *(const float2*)&g_h2[sA.x * CH + lane * 2];
            u1.f = *(const float2*)&g_h2[sA.y * CH + lane * 2];
            u2.f = *(const float2*)&g_h2[sA.z * CH + lane * 2];
            u3.f = *(const float2*)&g_h2[sA.w * CH + lane * 2];
            u4.f = *(const float2*)&g_h2[sB.x * CH + lane * 2];
            u5.f = *(const float2*)&g_h2[sB.y * CH + lane * 2];
            u6.f = *(const float2*)&g_h2[sB.z * CH + lane * 2];
            u7.f = *(const float2*)&g_h2[sB.w * CH + lane * 2];
            float4 eA = *(const float4*)&exrow[j];
            float4 eB = *(const float4*)&exrow[j + 4];
            ffma2(acc, bc2(eA.x), u0.u); ffma2(acc, bc2(eA.y), u1.u);
            ffma2(acc, bc2(eA.z), u2.u); ffma2(acc, bc2(eA.w), u3.u);
            ffma2(acc, bc2(eB.x), u4.u); ffma2(acc, bc2(eB.y), u5.u);
            ffma2(acc, bc2(eB.z), u6.u); ffma2(acc, bc2(eB.w), u7.u);
        }
    } else {
        float den = exself;
        for (int base = 0; base < cnt; base += 32) {
            int idx = base + lane;
            float ex = 0.f;
            if (idx < cnt) ex = __expf(lrelu(g_asrc2[g_slot[start + idx]] + ad));
#pragma unroll
            for (int o = 16; o > 0; o >>= 1)
                ex += __shfl_xor_sync(0xffffffffu, ex, o);
            den += ex;
        }
        rden = 1.f / (den + 1e-16f);
        {
            F2U us;
            us.f = *(const float2*)&g_h2[w * CH + lane * 2];
            ffma2(acc, bc2(exself), us.u);
        }
        for (int base = 0; base < cnt; base += 32) {
            int idx = base + lane;
            int s = w;
            float al = 0.f;
            if (idx < cnt) {
                s = g_slot[start + idx];
                al = __expf(lrelu(g_asrc2[s] + ad));
            }
            int c = min(32, cnt - base);
            for (int j = 0; j < c; j++) {
                int sj = __shfl_sync(0xffffffffu, s, j);
                float af = __shfl_sync(0xffffffffu, al, j);
                F2U u;
                u.f = *(const float2*)&g_h2[sj * CH + lane * 2];
                ffma2(acc, bc2(af), u.u);
            }
        }
    }
    fmul2(acc, bc2(rden));
    float a0, a1;
    unpk2(acc, a0, a1);
    float2 bv = *(const float2*)&b2[lane * 2];
    *(float2*)&dout[w * CH + lane * 2] = make_float2(a0 + bv.x, a1 + bv.y);
}

// ---------------- stream/event resources (created at load time) --------------
struct SideRes {
    cudaStream_t stream;
    cudaEvent_t ev_fork, ev_join;
    SideRes() {
        cudaStreamCreateWithFlags(&stream, cudaStreamNonBlocking);
        cudaEventCreateWithFlags(&ev_fork, cudaEventDisableTiming);
        cudaEventCreateWithFlags(&ev_join, cudaEventDisableTiming);
    }
};
static SideRes g_res;

// ---------------- launch -----------------------------------------------------
extern "C" void kernel_launch(void* const* d_in, const int* in_sizes, int n_in,
                              void* d_out, int out_size) {
    const float* x      = (const float*)d_in[0];
    const int*   ei     = (const int*)  d_in[1];
    const float* pe     = (const float*)d_in[2];
    const float* W1     = (const float*)d_in[3];
    const float* a_src1 = (const float*)d_in[4];
    const float* a_dst1 = (const float*)d_in[5];
    const float* b1     = (const float*)d_in[6];
    const float* W2     = (const float*)d_in[7];
    const float* a_src2 = (const float*)d_in[8];
    const float* a_dst2 = (const float*)d_in[9];
    const float* b2     = (const float*)d_in[10];
    float* out = (float*)d_out;

    // fork: adjacency build runs concurrently with GEMM1
    cudaEventRecord(g_res.ev_fork, 0);
    cudaStreamWaitEvent(g_res.stream, g_res.ev_fork, 0);
    k_zero<<<16, 256, 0, g_res.stream>>>();
    k_fill<<<E_EDGES / 256, 256, 0, g_res.stream>>>(ei);
    cudaEventRecord(g_res.ev_join, g_res.stream);

    k_gemm1<<<dim3(N_NODES / 64, HEADS), 128>>>(x, pe, W1, a_src1, a_dst1);

    // join, then the dependent chain
    cudaStreamWaitEvent(0, g_res.ev_join, 0);
    k_agg1<<<N_NODES / 8, 256>>>();
    k_gemm2<<<N_NODES / 64, 128>>>(b1, W2, a_src2, a_dst2);
    k_agg2<<<N_NODES / 8, 256>>>(out, b2);
}

// round 8
// speedup vs baseline: 1.5601x; 1.5601x over previous
#include <cuda_runtime.h>
#include <cuda_fp16.h>
#include <cstdint>

#define N_NODES 16384
#define D_IN 128
#define SEQL 128
#define HEADS 4
#define CH 64
#define F1 256
#define E_EDGES 262144
#define CAP 64           // slots per destination (P(deg>64) ~ 1e-19)

// ---------------- scratch (static device globals; no allocation) -------------
__device__ __half g_h1h[N_NODES * F1];    // layer-1 features (fp16, gather-only)
__device__ float g_out1[N_NODES * F1];    // layer-1 aggregation result
__device__ float g_asrc1[N_NODES * HEADS];
__device__ float g_adst1[N_NODES * HEADS];
__device__ float g_h2[N_NODES * CH];      // layer-2 features
__device__ float g_asrc2[N_NODES];
__device__ float g_adst2[N_NODES];
// slotted adjacency (dst-binned; self-loops handled implicitly)
__device__ int g_cur[N_NODES];
__device__ int g_slot[N_NODES * CAP];

__device__ __forceinline__ float lrelu(float v) { return v > 0.f ? v : 0.2f * v; }
__device__ __forceinline__ float elu1(float v) { return v > 0.f ? v : expm1f(v); }
__device__ __forceinline__ uint32_t h2u(__half2 h) { return *reinterpret_cast<uint32_t*>(&h); }

// ---- packed f32x2 helpers (sm_100+) ----
typedef unsigned long long ull;
__device__ __forceinline__ void ffma2(ull& acc, ull a, ull b) {
    asm("fma.rn.f32x2 %0, %1, %2, %0;" : "+l"(acc) : "l"(a), "l"(b));
}
__device__ __forceinline__ ull bc2(float x) {
    ull r;
    unsigned u = __float_as_uint(x);
    asm("mov.b64 %0, {%1, %1};" : "=l"(r) : "r"(u));
    return r;
}
__device__ __forceinline__ void unpk2(ull v, float& lo, float& hi) {
    asm("mov.b64 {%0, %1}, %2;" : "=f"(lo), "=f"(hi) : "l"(v));
}
union F2U { float2 f; ull u; };

// fp16 uint4 (8 values) * scalar -> 4 packed f32x2 accumulators
__device__ __forceinline__ void hacc(ull* acc2, uint4 v, float af) {
    ull a = bc2(af);
    F2U c0, c1, c2, c3;
    c0.f = __half22float2(*(__half2*)&v.x);
    c1.f = __half22float2(*(__half2*)&v.y);
    c2.f = __half22float2(*(__half2*)&v.z);
    c3.f = __half22float2(*(__half2*)&v.w);
    ffma2(acc2[0], a, c0.u);
    ffma2(acc2[1], a, c1.u);
    ffma2(acc2[2], a, c2.u);
    ffma2(acc2[3], a, c3.u);
}

// ---------------- adjacency build --------------------------------------------
__global__ void k_zero() {
    int i = blockIdx.x * blockDim.x + threadIdx.x;     // 4096 threads
    *(int4*)&g_cur[i * 4] = make_int4(0, 0, 0, 0);
}
__global__ void k_fill(const int* __restrict__ ei) {
    int e = blockIdx.x * blockDim.x + threadIdx.x;     // 262144 threads
    int ss = ei[e];
    int dd = ei[E_EDGES + e];
    int pos = atomicAdd(&g_cur[dd], 1);
    if (pos < CAP) g_slot[(dd << 6) + pos] = ss;
}

// ---------------- GEMM1: h1 = (x*sqrt(D) + pe) @ W1, fused alpha dots --------
// BM=64, BN=64(head), BK=32, 128 threads, microtile 8 rows x 4 cols, FFMA2.
__global__ void __launch_bounds__(128) k_gemm1(
        const float* __restrict__ x, const float* __restrict__ pe,
        const float* __restrict__ W1,
        const float* __restrict__ a_src1, const float* __restrict__ a_dst1) {
    const int head = blockIdx.y;
    const int rowBase = blockIdx.x * 64;
    __shared__ float Ak[32][64];      // K-major
    __shared__ float Bs[32][64];
    __shared__ float sa[64], sd[64];

    const int tid = threadIdx.x;
    const int tx = tid & 15;          // col quad: cols tx*4..+3
    const int ty = tid >> 4;          // row octet: rows ty*8..+7
    if (tid < 64) { sa[tid] = a_src1[head * 64 + tid]; sd[tid] = a_dst1[head * 64 + tid]; }

    ull acc2[4][4];
#pragma unroll
    for (int i = 0; i < 4; i++)
#pragma unroll
        for (int j = 0; j < 4; j++) acc2[i][j] = 0ull;

    const float SC = 11.313708498984760f; // sqrt(128)
    const int ar = tid & 63;              // A fill: row
    const int kb = (tid >> 6) * 16;       // A fill: k half (16 floats)
    const float* xr = x + (rowBase + ar) * D_IN;
    const float* pr = pe + ((rowBase + ar) & (SEQL - 1)) * D_IN;

    for (int k0 = 0; k0 < D_IN; k0 += 32) {
#pragma unroll
        for (int q = 0; q < 4; q++) {
            float4 xv = *(const float4*)&xr[k0 + kb + q * 4];
            float4 pv = *(const float4*)&pr[k0 + kb + q * 4];
            Ak[kb + q * 4 + 0][ar] = xv.x * SC + pv.x;
            Ak[kb + q * 4 + 1][ar] = xv.y * SC + pv.y;
            Ak[kb + q * 4 + 2][ar] = xv.z * SC + pv.z;
            Ak[kb + q * 4 + 3][ar] = xv.w * SC + pv.w;
        }
#pragma unroll
        for (int q = 0; q < 4; q++) {
            int v = tid * 4 + q;      // 0..511
            int r = v >> 4, c = v & 15;
            *(float4*)&Bs[r][c * 4] = *(const float4*)&W1[(k0 + r) * F1 + head * 64 + c * 4];
        }
        __syncthreads();
#pragma unroll
        for (int kk = 0; kk < 32; kk++) {
            ulonglong2 ap01 = *(ulonglong2*)&Ak[kk][ty * 8];      // row pairs 0,1
            ulonglong2 ap23 = *(ulonglong2*)&Ak[kk][ty * 8 + 4];  // row pairs 2,3
            float4 bv = *(float4*)&Bs[kk][tx * 4];
            ull b0 = bc2(bv.x), b1 = bc2(bv.y), b2 = bc2(bv.z), b3 = bc2(bv.w);
            ffma2(acc2[0][0], ap01.x, b0); ffma2(acc2[0][1], ap01.x, b1);
            ffma2(acc2[0][2], ap01.x, b2); ffma2(acc2[0][3], ap01.x, b3);
            ffma2(acc2[1][0], ap01.y, b0); ffma2(acc2[1][1], ap01.y, b1);
            ffma2(acc2[1][2], ap01.y, b2); ffma2(acc2[1][3], ap01.y, b3);
            ffma2(acc2[2][0], ap23.x, b0); ffma2(acc2[2][1], ap23.x, b1);
            ffma2(acc2[2][2], ap23.x, b2); ffma2(acc2[2][3], ap23.x, b3);
            ffma2(acc2[3][0], ap23.y, b0); ffma2(acc2[3][1], ap23.y, b1);
            ffma2(acc2[3][2], ap23.y, b2); ffma2(acc2[3][3], ap23.y, b3);
        }
        __syncthreads();
    }

    // epilogue: per row-pair, fp16 store + alpha dots (reduce over 16 tx lanes)
#pragma unroll
    for (int rp = 0; rp < 4; rp++) {
        float alo[4], ahi[4];
#pragma unroll
        for (int c = 0; c < 4; c++) unpk2(acc2[rp][c], alo[c], ahi[c]);
        int rlo = rowBase + ty * 8 + rp * 2;
        int rhi = rlo + 1;
        __half2 l0 = __floats2half2_rn(alo[0], alo[1]);
        __half2 l1 = __floats2half2_rn(alo[2], alo[3]);
        __half2 h0 = __floats2half2_rn(ahi[0], ahi[1]);
        __half2 h1 = __floats2half2_rn(ahi[2], ahi[3]);
        *(uint2*)&g_h1h[rlo * F1 + head * 64 + tx * 4] = make_uint2(h2u(l0), h2u(l1));
        *(uint2*)&g_h1h[rhi * F1 + head * 64 + tx * 4] = make_uint2(h2u(h0), h2u(h1));
        float pslo = 0.f, pdlo = 0.f, pshi = 0.f, pdhi = 0.f;
#pragma unroll
        for (int c = 0; c < 4; c++) {
            float wa = sa[tx * 4 + c], wd = sd[tx * 4 + c];
            pslo += alo[c] * wa; pdlo += alo[c] * wd;
            pshi += ahi[c] * wa; pdhi += ahi[c] * wd;
        }
#pragma unroll
        for (int o = 1; o < 16; o <<= 1) {
            pslo += __shfl_xor_sync(0xffffffffu, pslo, o);
            pdlo += __shfl_xor_sync(0xffffffffu, pdlo, o);
            pshi += __shfl_xor_sync(0xffffffffu, pshi, o);
            pdhi += __shfl_xor_sync(0xffffffffu, pdhi, o);
        }
        if (tx == 0) {
            g_asrc1[rlo * HEADS + head] = pslo;
            g_adst1[rlo * HEADS + head] = pdlo;
            g_asrc1[rhi * HEADS + head] = pshi;
            g_adst1[rhi * HEADS + head] = pdhi;
        }
    }
}

// ---------------- layer-1 fused softmax + aggregate (warp per dst) -----------
__global__ void __launch_bounds__(256) k_agg1() {
    __shared__ float s_al[8][4][40];   // [warp][head][entry]
    __shared__ int s_src[8][40];
    const int wip = threadIdx.x >> 5;
    const int w = (blockIdx.x * blockDim.x + threadIdx.x) >> 5;
    const int lane = threadIdx.x & 31;
    if (w >= N_NODES) return;
    const int start = w << 6;
    const int cnt = min(g_cur[w], CAP);
    const float4 ad = *(const float4*)&g_adst1[w * 4];
    const float4 asw = *(const float4*)&g_asrc1[w * 4];
    const float4 exself = make_float4(__expf(lrelu(asw.x + ad.x)), __expf(lrelu(asw.y + ad.y)),
                                      __expf(lrelu(asw.z + ad.z)), __expf(lrelu(asw.w + ad.w)));
    const int h = lane >> 3;
    ull acc2[4] = {0ull, 0ull, 0ull, 0ull};

    if (cnt <= 32) {
        // ---- fast path: self folded in as entry 0, edges at 1..cnt, zero pads ----
        int s = w;
        float4 ex = make_float4(0.f, 0.f, 0.f, 0.f);
        if (lane < cnt) {
            s = g_slot[start + lane];
            float4 as = *(const float4*)&g_asrc1[s * 4];
            ex = make_float4(__expf(lrelu(as.x + ad.x)), __expf(lrelu(as.y + ad.y)),
                             __expf(lrelu(as.z + ad.z)), __expf(lrelu(as.w + ad.w)));
        }
        float4 den = ex;
#pragma unroll
        for (int o = 16; o > 0; o >>= 1) {
            den.x += __shfl_xor_sync(0xffffffffu, den.x, o);
            den.y += __shfl_xor_sync(0xffffffffu, den.y, o);
            den.z += __shfl_xor_sync(0xffffffffu, den.z, o);
            den.w += __shfl_xor_sync(0xffffffffu, den.w, o);
        }
        den.x += exself.x; den.y += exself.y; den.z += exself.z; den.w += exself.w;
        const float4 rden = make_float4(1.f / (den.x + 1e-16f), 1.f / (den.y + 1e-16f),
                                        1.f / (den.z + 1e-16f), 1.f / (den.w + 1e-16f));
        // pads: entries 33..35
        if (lane < 16 && (lane & 3) != 0) s_al[wip][lane >> 2][32 + (lane & 3)] = 0.f;
        if (lane >= 16 && lane < 19) s_src[wip][17 + lane] = w;   // 33..35
        // edges -> entry lane+1
        s_al[wip][0][lane + 1] = ex.x * rden.x;
        s_al[wip][1][lane + 1] = ex.y * rden.y;
        s_al[wip][2][lane + 1] = ex.z * rden.z;
        s_al[wip][3][lane + 1] = ex.w * rden.w;
        s_src[wip][lane + 1] = s;
        if (lane == 0) {
            s_src[wip][0] = w;
            s_al[wip][0][0] = exself.x * rden.x;
            s_al[wip][1][0] = exself.y * rden.y;
            s_al[wip][2][0] = exself.z * rden.z;
            s_al[wip][3][0] = exself.w * rden.w;
        }
        __syncwarp();

        const int tp = (cnt + 1 + 3) & ~3;
        const float* alrow = &s_al[wip][h][0];
        const int* srow = &s_src[wip][0];
        for (int j = 0; j < tp; j += 4) {
            float4 af4 = *(const float4*)&alrow[j];
            int4 s4 = *(const int4*)&srow[j];
            uint4 v0 = *(const uint4*)&g_h1h[s4.x * F1 + lane * 8];
            uint4 v1 = *(const uint4*)&g_h1h[s4.y * F1 + lane * 8];
            uint4 v2 = *(const uint4*)&g_h1h[s4.z * F1 + lane * 8];
            uint4 v3 = *(const uint4*)&g_h1h[s4.w * F1 + lane * 8];
            hacc(acc2, v0, af4.x);
            hacc(acc2, v1, af4.y);
            hacc(acc2, v2, af4.z);
            hacc(acc2, v3, af4.w);
        }
    } else {
        // ---- general path (rare: 32 < deg <= 64) ----
        float4 den = exself;
        for (int base = 0; base < cnt; base += 32) {
            int idx = base + lane;
            float4 ex = make_float4(0.f, 0.f, 0.f, 0.f);
            if (idx < cnt) {
                int s = g_slot[start + idx];
                float4 as = *(const float4*)&g_asrc1[s * 4];
                ex = make_float4(__expf(lrelu(as.x + ad.x)), __expf(lrelu(as.y + ad.y)),
                                 __expf(lrelu(as.z + ad.z)), __expf(lrelu(as.w + ad.w)));
            }
#pragma unroll
            for (int o = 16; o > 0; o >>= 1) {
                ex.x += __shfl_xor_sync(0xffffffffu, ex.x, o);
                ex.y += __shfl_xor_sync(0xffffffffu, ex.y, o);
                ex.z += __shfl_xor_sync(0xffffffffu, ex.z, o);
                ex.w += __shfl_xor_sync(0xffffffffu, ex.w, o);
            }
            den.x += ex.x; den.y += ex.y; den.z += ex.z; den.w += ex.w;
        }
        const float4 rden = make_float4(1.f / (den.x + 1e-16f), 1.f / (den.y + 1e-16f),
                                        1.f / (den.z + 1e-16f), 1.f / (den.w + 1e-16f));
        float exh = (h & 2) ? ((h & 1) ? exself.w : exself.z) : ((h & 1) ? exself.y : exself.x);
        float rdh = (h & 2) ? ((h & 1) ? rden.w : rden.z) : ((h & 1) ? rden.y : rden.x);
        {   // self
            uint4 v = *(const uint4*)&g_h1h[w * F1 + lane * 8];
            hacc(acc2, v, exh * rdh);
        }
        for (int base = 0; base < cnt; base += 32) {
            int idx = base + lane;
            int s = w;
            float4 al = make_float4(0.f, 0.f, 0.f, 0.f);
            if (idx < cnt) {
                s = g_slot[start + idx];
                float4 as = *(const float4*)&g_asrc1[s * 4];
                al = make_float4(__expf(lrelu(as.x + ad.x)) * rden.x,
                                 __expf(lrelu(as.y + ad.y)) * rden.y,
                                 __expf(lrelu(as.z + ad.z)) * rden.z,
                                 __expf(lrelu(as.w + ad.w)) * rden.w);
            }
            __syncwarp();
            s_al[wip][0][lane] = al.x; s_al[wip][1][lane] = al.y;
            s_al[wip][2][lane] = al.z; s_al[wip][3][lane] = al.w;
            s_src[wip][lane] = s;
            __syncwarp();
            int c = min(32, cnt - base);
            int cp = (c + 3) & ~3;
            const float* alrow = &s_al[wip][h][0];
            const int* srow = &s_src[wip][0];
            for (int j = 0; j < cp; j += 4) {
                float4 af4 = *(const float4*)&alrow[j];
                int4 s4 = *(const int4*)&srow[j];
                uint4 v0 = *(const uint4*)&g_h1h[s4.x * F1 + lane * 8];
                uint4 v1 = *(const uint4*)&g_h1h[s4.y * F1 + lane * 8];
                uint4 v2 = *(const uint4*)&g_h1h[s4.z * F1 + lane * 8];
                uint4 v3 = *(const uint4*)&g_h1h[s4.w * F1 + lane * 8];
                hacc(acc2, v0, af4.x);
                hacc(acc2, v1, af4.y);
                hacc(acc2, v2, af4.z);
                hacc(acc2, v3, af4.w);
            }
            __syncwarp();
        }
    }
    float o0, o1, o2, o3, o4, o5, o6, o7;
    unpk2(acc2[0], o0, o1); unpk2(acc2[1], o2, o3);
    unpk2(acc2[2], o4, o5); unpk2(acc2[3], o6, o7);
    *(float4*)&g_out1[w * F1 + lane * 8] = make_float4(o0, o1, o2, o3);
    *(float4*)&g_out1[w * F1 + lane * 8 + 4] = make_float4(o4, o5, o6, o7);
}

// ---------------- GEMM2: h2 = elu(out1 + b1) @ W2, fused alpha dots ----------
__global__ void __launch_bounds__(128) k_gemm2(
        const float* __restrict__ b1, const float* __restrict__ W2,
        const float* __restrict__ a_src2, const float* __restrict__ a_dst2) {
    const int rowBase = blockIdx.x * 64;
    __shared__ float Ak[32][64];      // K-major
    __shared__ float Bs[32][64];
    __shared__ float sa[64], sd[64];
    __shared__ float sb1[F1];

    const int tid = threadIdx.x;
    const int tx = tid & 15;
    const int ty = tid >> 4;
    if (tid < 64) { sa[tid] = a_src2[tid]; sd[tid] = a_dst2[tid]; }
    sb1[tid] = b1[tid];
    sb1[tid + 128] = b1[tid + 128];
    __syncthreads();

    ull acc2[4][4];
#pragma unroll
    for (int i = 0; i < 4; i++)
#pragma unroll
        for (int j = 0; j < 4; j++) acc2[i][j] = 0ull;

    const int ar = tid & 63;
    const int kb = (tid >> 6) * 16;
    const float* orow = g_out1 + (rowBase + ar) * F1;

    for (int k0 = 0; k0 < F1; k0 += 32) {
#pragma unroll
        for (int q = 0; q < 4; q++) {
            float4 ov = *(const float4*)&orow[k0 + kb + q * 4];
            Ak[kb + q * 4 + 0][ar] = elu1(ov.x + sb1[k0 + kb + q * 4 + 0]);
            Ak[kb + q * 4 + 1][ar] = elu1(ov.y + sb1[k0 + kb + q * 4 + 1]);
            Ak[kb + q * 4 + 2][ar] = elu1(ov.z + sb1[k0 + kb + q * 4 + 2]);
            Ak[kb + q * 4 + 3][ar] = elu1(ov.w + sb1[k0 + kb + q * 4 + 3]);
        }
#pragma unroll
        for (int q = 0; q < 4; q++) {
            int v = tid * 4 + q;
            int r = v >> 4, c = v & 15;
            *(float4*)&Bs[r][c * 4] = *(const float4*)&W2[(k0 + r) * CH + c * 4];
        }
        __syncthreads();
#pragma unroll
        for (int kk = 0; kk < 32; kk++) {
            ulonglong2 ap01 = *(ulonglong2*)&Ak[kk][ty * 8];
            ulonglong2 ap23 = *(ulonglong2*)&Ak[kk][ty * 8 + 4];
            float4 bv = *(float4*)&Bs[kk][tx * 4];
            ull b0 = bc2(bv.x), b1v = bc2(bv.y), b2 = bc2(bv.z), b3 = bc2(bv.w);
            ffma2(acc2[0][0], ap01.x, b0); ffma2(acc2[0][1], ap01.x, b1v);
            ffma2(acc2[0][2], ap01.x, b2); ffma2(acc2[0][3], ap01.x, b3);
            ffma2(acc2[1][0], ap01.y, b0); ffma2(acc2[1][1], ap01.y, b1v);
            ffma2(acc2[1][2], ap01.y, b2); ffma2(acc2[1][3], ap01.y, b3);
            ffma2(acc2[2][0], ap23.x, b0); ffma2(acc2[2][1], ap23.x, b1v);
            ffma2(acc2[2][2], ap23.x, b2); ffma2(acc2[2][3], ap23.x, b3);
            ffma2(acc2[3][0], ap23.y, b0); ffma2(acc2[3][1], ap23.y, b1v);
            ffma2(acc2[3][2], ap23.y, b2); ffma2(acc2[3][3], ap23.y, b3);
        }
        __syncthreads();
    }

#pragma unroll
    for (int rp = 0; rp < 4; rp++) {
        float alo[4], ahi[4];
#pragma unroll
        for (int c = 0; c < 4; c++) unpk2(acc2[rp][c], alo[c], ahi[c]);
        int rlo = rowBase + ty * 8 + rp * 2;
        int rhi = rlo + 1;
        *(float4*)&g_h2[rlo * CH + tx * 4] = make_float4(alo[0], alo[1], alo[2], alo[3]);
        *(float4*)&g_h2[rhi * CH + tx * 4] = make_float4(ahi[0], ahi[1], ahi[2], ahi[3]);
        float pslo = 0.f, pdlo = 0.f, pshi = 0.f, pdhi = 0.f;
#pragma unroll
        for (int c = 0; c < 4; c++) {
            float wa = sa[tx * 4 + c], wd = sd[tx * 4 + c];
            pslo += alo[c] * wa; pdlo += alo[c] * wd;
            pshi += ahi[c] * wa; pdhi += ahi[c] * wd;
        }
#pragma unroll
        for (int o = 1; o < 16; o <<= 1) {
            pslo += __shfl_xor_sync(0xffffffffu, pslo, o);
            pdlo += __shfl_xor_sync(0xffffffffu, pdlo, o);
            pshi += __shfl_xor_sync(0xffffffffu, pshi, o);
            pdhi += __shfl_xor_sync(0xffffffffu, pdhi, o);
        }
        if (tx == 0) {
            g_asrc2[rlo] = pslo; g_adst2[rlo] = pdlo;
            g_asrc2[rhi] = pshi; g_adst2[rhi] = pdhi;
        }
    }
}

// ---------------- layer-2 fused softmax + aggregate (warp per dst) -----------
__global__ void k_agg2(float* __restrict__ dout, const float* __restrict__ b2) {
    const int w = (blockIdx.x * blockDim.x + threadIdx.x) >> 5;
    const int lane = threadIdx.x & 31;
    if (w >= N_NODES) return;
    const int start = w << 6;
    const int cnt = min(g_cur[w], CAP);
    const float ad = g_adst2[w];
    const float exself = __expf(lrelu(g_asrc2[w] + ad));
    float a0, a1;

    if (cnt <= 32) {
        int s = 0;
        float ex = 0.f;
        if (lane < cnt) {
            s = g_slot[start + lane];
            ex = __expf(lrelu(g_asrc2[s] + ad));
        }
        float den = ex;
#pragma unroll
        for (int o = 16; o > 0; o >>= 1)
            den += __shfl_xor_sync(0xffffffffu, den, o);
        den += exself;
        const float rden = 1.f / (den + 1e-16f);
        float al = ex * rden;
        {
            float afs = exself * rden;
            float2 hv = *(const float2*)&g_h2[w * CH + lane * 2];
            a0 = hv.x * afs; a1 = hv.y * afs;
        }
        if (cnt > 0) {
            int s0 = __shfl_sync(0xffffffffu, s, 0);
            float2 v = *(const float2*)&g_h2[s0 * CH + lane * 2];
            for (int j = 0; j < cnt; j++) {
                float2 vn = v;
                if (j + 1 < cnt) {
                    int sn = __shfl_sync(0xffffffffu, s, j + 1);
                    vn = *(const float2*)&g_h2[sn * CH + lane * 2];
                }
                float af = __shfl_sync(0xffffffffu, al, j);
                a0 += v.x * af; a1 += v.y * af;
                v = vn;
            }
        }
    } else {
        float den = exself;
        for (int base = 0; base < cnt; base += 32) {
            int idx = base + lane;
            float ex = 0.f;
            if (idx < cnt) ex = __expf(lrelu(g_asrc2[g_slot[start + idx]] + ad));
#pragma unroll
            for (int o = 16; o > 0; o >>= 1)
                ex += __shfl_xor_sync(0xffffffffu, ex, o);
            den += ex;
        }
        const float rden = 1.f / (den + 1e-16f);
        {
            float afs = exself * rden;
            float2 hv = *(const float2*)&g_h2[w * CH + lane * 2];
            a0 = hv.x * afs; a1 = hv.y * afs;
        }
        for (int base = 0; base < cnt; base += 32) {
            int idx = base + lane;
            int s = 0;
            float al = 0.f;
            if (idx < cnt) {
                s = g_slot[start + idx];
                al = __expf(lrelu(g_asrc2[s] + ad)) * rden;
            }
            int c = min(32, cnt - base);
            for (int j = 0; j < c; j++) {
                int sj = __shfl_sync(0xffffffffu, s, j);
                float af = __shfl_sync(0xffffffffu, al, j);
                float2 hv = *(const float2*)&g_h2[sj * CH + lane * 2];
                a0 += hv.x * af;
                a1 += hv.y * af;
            }
        }
    }
    float2 bv = *(const float2*)&b2[lane * 2];
    *(float2*)&dout[w * CH + lane * 2] = make_float2(a0 + bv.x, a1 + bv.y);
}

// ---------------- stream/event resources (created at load time) --------------
struct SideRes {
    cudaStream_t stream;
    cudaEvent_t ev_fork, ev_join;
    SideRes() {
        cudaStreamCreateWithFlags(&stream, cudaStreamNonBlocking);
        cudaEventCreateWithFlags(&ev_fork, cudaEventDisableTiming);
        cudaEventCreateWithFlags(&ev_join, cudaEventDisableTiming);
    }
};
static SideRes g_res;

// ---------------- launch -----------------------------------------------------
extern "C" void kernel_launch(void* const* d_in, const int* in_sizes, int n_in,
                              void* d_out, int out_size) {
    const float* x      = (const float*)d_in[0];
    const int*   ei     = (const int*)  d_in[1];
    const float* pe     = (const float*)d_in[2];
    const float* W1     = (const float*)d_in[3];
    const float* a_src1 = (const float*)d_in[4];
    const float* a_dst1 = (const float*)d_in[5];
    const float* b1     = (const float*)d_in[6];
    const float* W2     = (const float*)d_in[7];
    const float* a_src2 = (const float*)d_in[8];
    const float* a_dst2 = (const float*)d_in[9];
    const float* b2     = (const float*)d_in[10];
    float* out = (float*)d_out;

    // fork: adjacency build runs concurrently with GEMM1
    cudaEventRecord(g_res.ev_fork, 0);
    cudaStreamWaitEvent(g_res.stream, g_res.ev_fork, 0);
    k_zero<<<16, 256, 0, g_res.stream>>>();
    k_fill<<<E_EDGES / 256, 256, 0, g_res.stream>>>(ei);
    cudaEventRecord(g_res.ev_join, g_res.stream);

    k_gemm1<<<dim3(N_NODES / 64, HEADS), 128>>>(x, pe, W1, a_src1, a_dst1);

    // join, then the dependent chain
    cudaStreamWaitEvent(0, g_res.ev_join, 0);
    k_agg1<<<N_NODES / 8, 256>>>();
    k_gemm2<<<N_NODES / 64, 128>>>(b1, W2, a_src2, a_dst2);
    k_agg2<<<N_NODES / 8, 256>>>(out, b2);
}